// round 1
// baseline (speedup 1.0000x reference)
#include <cuda_runtime.h>
#include <cuda_bf16.h>
#include <math.h>

// Problem constants (match reference)
#define MAXN 10000
#define MAXE 40000
#define MAXG 128
#define NF 92
#define EF 50
#define HD 64
#define NHEAD 10
#define GD 108
#define NL 5
#define HW (NHEAD*HD)   // 640

// ---------------- static device scratch (no allocations allowed) -------------
__device__ float g_h[MAXN*HD];       // current node features
__device__ float g_h0[MAXN*HD];      // initial embedding (residual)
__device__ float g_ea[MAXE*HD];      // edge embedding
__device__ float g_P[MAXN*HW];       // h @ W_top      (per layer)
__device__ float g_Q[(size_t)MAXE*HW]; // ea @ W_bot   (per layer)
__device__ float g_hagg[MAXN*HD];    // aggregated messages
__device__ float g_GB[MAXG*HD];      // global_features @ ga_W1[64:] + b1
__device__ float g_score[MAXN];
__device__ float g_ex[MAXN];
__device__ unsigned g_smax[MAXG];    // ordered-float max keys
__device__ float g_denom[MAXG];
__device__ float g_pooled[MAXG*HD];

__device__ __forceinline__ float lrelu(float v) { return v > 0.f ? v : 0.2f * v; }

__device__ __forceinline__ unsigned f2o(float f) {
    unsigned u = __float_as_uint(f);
    return (u & 0x80000000u) ? ~u : (u | 0x80000000u);
}
__device__ __forceinline__ float o2f(unsigned u) {
    return (u & 0x80000000u) ? __uint_as_float(u ^ 0x80000000u) : __uint_as_float(~u);
}

// ---------------- tiled fp32 GEMM: C[M,Nc] = act(A[M,K] @ W[K,Nc] + bias) ----
// 64x64 tile, K chunks of 16, 256 threads, 4x4 microtile per thread.
__global__ void gemm_tiled(const float* __restrict__ A, int lda,
                           const float* __restrict__ W, int ldw,
                           const float* __restrict__ bias,
                           float* __restrict__ C, int ldc,
                           int M, int K, int act)
{
    __shared__ float As[16][64];
    __shared__ float Ws[16][64];
    const int row0 = blockIdx.x * 64;
    const int col0 = blockIdx.y * 64;
    const int tid = threadIdx.x;
    const int tx = tid & 15, ty = tid >> 4;

    float acc[4][4];
#pragma unroll
    for (int i = 0; i < 4; i++)
#pragma unroll
        for (int j = 0; j < 4; j++) acc[i][j] = 0.f;

    for (int k0 = 0; k0 < K; k0 += 16) {
#pragma unroll
        for (int i = 0; i < 4; i++) {
            int e = tid + 256 * i;
            int r = e >> 4, kk = e & 15;
            int gr = row0 + r, gk = k0 + kk;
            As[kk][r] = (gr < M && gk < K) ? A[(size_t)gr * lda + gk] : 0.f;
        }
#pragma unroll
        for (int i = 0; i < 4; i++) {
            int e = tid + 256 * i;
            int kk = e >> 6, c = e & 63;
            int gk = k0 + kk;
            Ws[kk][c] = (gk < K) ? W[(size_t)gk * ldw + col0 + c] : 0.f;
        }
        __syncthreads();
#pragma unroll
        for (int kk = 0; kk < 16; kk++) {
            float4 a = *(const float4*)&As[kk][ty * 4];
            float4 b = *(const float4*)&Ws[kk][tx * 4];
            float av[4] = {a.x, a.y, a.z, a.w};
            float bv[4] = {b.x, b.y, b.z, b.w};
#pragma unroll
            for (int i = 0; i < 4; i++)
#pragma unroll
                for (int j = 0; j < 4; j++) acc[i][j] += av[i] * bv[j];
        }
        __syncthreads();
    }
#pragma unroll
    for (int i = 0; i < 4; i++) {
        int r = row0 + ty * 4 + i;
        if (r >= M) continue;
#pragma unroll
        for (int j = 0; j < 4; j++) {
            int c = col0 + tx * 4 + j;
            float v = acc[i][j];
            if (bias) v += bias[c];
            if (act) v = lrelu(v);
            C[(size_t)r * ldc + c] = v;
        }
    }
}

// ---------------- per-edge GAT kernel (one warp per edge) --------------------
__global__ void edge_kernel(const int* __restrict__ row, const int* __restrict__ col,
                            const float* __restrict__ att,    // [NHEAD][128]
                            const float* __restrict__ gamma,  // [NHEAD]
                            const float* __restrict__ beta,   // [NHEAD]
                            int E)
{
    int e = (blockIdx.x * blockDim.x + threadIdx.x) >> 5;
    if (e >= E) return;
    const int l = threadIdx.x & 31;
    const int r = row[e], c = col[e];
    const float2* pr = (const float2*)(g_P + (size_t)r * HW);
    const float2* pc = (const float2*)(g_P + (size_t)c * HW);
    const float2* q  = (const float2*)(g_Q + (size_t)e * HW);
    const float2* at = (const float2*)att;   // head nh -> 64 float2

    float2 hj[NHEAD];
    float alpha[NHEAD];
#pragma unroll
    for (int nh = 0; nh < NHEAD; nh++) {
        float2 qv  = q[nh * 32 + l];
        float2 prv = pr[nh * 32 + l];
        float2 pcv = pc[nh * 32 + l];
        float hi0 = lrelu(prv.x + qv.x), hi1 = lrelu(prv.y + qv.y);
        float hj0 = lrelu(pcv.x + qv.x), hj1 = lrelu(pcv.y + qv.y);
        hj[nh].x = hj0; hj[nh].y = hj1;
        float2 a1 = at[nh * 64 + l];
        float2 a2 = at[nh * 64 + 32 + l];
        float part = hi0 * a1.x + hi1 * a1.y + hj0 * a2.x + hj1 * a2.y;
#pragma unroll
        for (int o = 16; o; o >>= 1) part += __shfl_xor_sync(0xffffffffu, part, o);
        alpha[nh] = part;
    }
    // lrelu -> groupnorm(eval) -> softmax over heads
    const float inv_std = 0.9999950000374997f;  // 1/sqrt(1+1e-5)
    float mx = -1e30f;
#pragma unroll
    for (int nh = 0; nh < NHEAD; nh++) {
        float a = lrelu(alpha[nh]);
        a = a * inv_std * gamma[nh] + beta[nh];
        alpha[nh] = a;
        mx = fmaxf(mx, a);
    }
    float s = 0.f;
#pragma unroll
    for (int nh = 0; nh < NHEAD; nh++) { float ev = expf(alpha[nh] - mx); alpha[nh] = ev; s += ev; }
    float inv = 0.1f / s;   // softmax normalizer * (1/NHEAD) head-mean
    float m0 = 0.f, m1 = 0.f;
#pragma unroll
    for (int nh = 0; nh < NHEAD; nh++) { m0 += hj[nh].x * alpha[nh]; m1 += hj[nh].y * alpha[nh]; }
    m0 *= inv; m1 *= inv;
    atomicAdd(&g_hagg[r * HD + 2 * l],     m0);
    atomicAdd(&g_hagg[r * HD + 2 * l + 1], m1);
}

// ---------------- node update ------------------------------------------------
__global__ void node_update(const float* __restrict__ b, int N, int first, int last)
{
    int idx = blockIdx.x * blockDim.x + threadIdx.x;
    if (idx >= N * HD) return;
    int k = idx & (HD - 1);
    float v = g_hagg[idx] + b[k];
    if (first) g_h[idx] = v;
    else       g_h[idx] = g_h[idx] + v;
    if (last)  g_h[idx] += g_h0[idx];
}

// ---------------- global-attention precompute: GB = gf @ W1[64:] + b1 --------
__global__ void gb_kernel(const float* __restrict__ gf, const float* __restrict__ W1,
                          const float* __restrict__ b1, int G)
{
    int g = blockIdx.x;
    int k = threadIdx.x;     // 64
    float acc = b1[k];
    const float* gr = gf + (size_t)g * GD;
    for (int j = 0; j < GD; j++) acc += gr[j] * W1[(64 + j) * HD + k];
    g_GB[g * HD + k] = acc;
}

// scores + segment max (warp per node)
__global__ void score_kernel(const int* __restrict__ batch,
                             const float* __restrict__ W1,
                             const float* __restrict__ W2, const float* __restrict__ b2,
                             int N)
{
    int n = (blockIdx.x * blockDim.x + threadIdx.x) >> 5;
    if (n >= N) return;
    int l = threadIdx.x & 31;
    int b = batch[n];
    int k0 = 2 * l;
    float s0 = g_GB[b * HD + k0], s1 = g_GB[b * HD + k0 + 1];
    const float* hr = g_h + (size_t)n * HD;
#pragma unroll 8
    for (int j = 0; j < HD; j++) {
        float hv = hr[j];
        s0 += hv * W1[j * HD + k0];
        s1 += hv * W1[j * HD + k0 + 1];
    }
    s0 = lrelu(s0); s1 = lrelu(s1);
    float part = s0 * W2[k0] + s1 * W2[k0 + 1];
#pragma unroll
    for (int o = 16; o; o >>= 1) part += __shfl_xor_sync(0xffffffffu, part, o);
    if (l == 0) {
        float sc = part + b2[0];
        g_score[n] = sc;
        atomicMax(&g_smax[b], f2o(sc));
    }
}

__global__ void exp_kernel(const int* __restrict__ batch, int N)
{
    int n = blockIdx.x * blockDim.x + threadIdx.x;
    if (n >= N) return;
    int b = batch[n];
    float ev = expf(g_score[n] - o2f(g_smax[b]));
    g_ex[n] = ev;
    atomicAdd(&g_denom[b], ev);
}

__global__ void pool_kernel(const int* __restrict__ batch, int N)
{
    int n = (blockIdx.x * blockDim.x + threadIdx.x) >> 5;
    if (n >= N) return;
    int l = threadIdx.x & 31;
    int b = batch[n];
    float w = g_ex[n] / g_denom[b];
    int k0 = 2 * l;
    atomicAdd(&g_pooled[b * HD + k0],     g_h[(size_t)n * HD + k0] * w);
    atomicAdd(&g_pooled[b * HD + k0 + 1], g_h[(size_t)n * HD + k0 + 1] * w);
}

__global__ void out_kernel(const float* __restrict__ W1, const float* __restrict__ b1,
                           const float* __restrict__ W2, const float* __restrict__ b2,
                           float* __restrict__ out)
{
    int g = blockIdx.x;
    int k = threadIdx.x;   // 64
    __shared__ float ps[HD];
    __shared__ float red[HD];
    ps[k] = g_pooled[g * HD + k];
    __syncthreads();
    float acc = b1[k];
#pragma unroll 8
    for (int j = 0; j < HD; j++) acc += ps[j] * W1[j * HD + k];
    acc = fmaxf(acc, 0.f);
    red[k] = acc * W2[k];
    __syncthreads();
    for (int o = 32; o; o >>= 1) {
        if (k < o) red[k] += red[k + o];
        __syncthreads();
    }
    if (k == 0) out[g] = red[0] + b2[0];
}

// ---------------- host launcher ---------------------------------------------
extern "C" void kernel_launch(void* const* d_in, const int* in_sizes, int n_in,
                              void* d_out, int out_size)
{
    const float* x      = (const float*)d_in[0];
    const int*   eidx   = (const int*)  d_in[1];
    const float* eattr  = (const float*)d_in[2];
    const int*   batch  = (const int*)  d_in[3];
    const float* gfeat  = (const float*)d_in[4];
    const float* node_W = (const float*)d_in[5];
    const float* node_b = (const float*)d_in[6];
    const float* edge_W = (const float*)d_in[7];
    const float* edge_b = (const float*)d_in[8];
    const float* conv_W = (const float*)d_in[9];
    const float* conv_att = (const float*)d_in[10];
    const float* conv_b = (const float*)d_in[11];
    const float* conv_g = (const float*)d_in[12];
    const float* conv_be = (const float*)d_in[13];
    const float* ga_W1  = (const float*)d_in[14];
    const float* ga_b1  = (const float*)d_in[15];
    const float* ga_W2  = (const float*)d_in[16];
    const float* ga_b2  = (const float*)d_in[17];
    const float* out_W1 = (const float*)d_in[18];
    const float* out_b1 = (const float*)d_in[19];
    const float* out_W2 = (const float*)d_in[20];
    const float* out_b2 = (const float*)d_in[21];

    const int N = in_sizes[3];
    const int E = in_sizes[2] / EF;
    const int G = in_sizes[4] / GD;

    const int* row = eidx;
    const int* col = eidx + E;

    float *p_h, *p_h0, *p_ea, *p_P, *p_Q, *p_hagg, *p_denom, *p_pooled;
    unsigned* p_smax;
    cudaGetSymbolAddress((void**)&p_h,     g_h);
    cudaGetSymbolAddress((void**)&p_h0,    g_h0);
    cudaGetSymbolAddress((void**)&p_ea,    g_ea);
    cudaGetSymbolAddress((void**)&p_P,     g_P);
    cudaGetSymbolAddress((void**)&p_Q,     g_Q);
    cudaGetSymbolAddress((void**)&p_hagg,  g_hagg);
    cudaGetSymbolAddress((void**)&p_smax,  g_smax);
    cudaGetSymbolAddress((void**)&p_denom, g_denom);
    cudaGetSymbolAddress((void**)&p_pooled,g_pooled);

    // embeddings
    {
        dim3 grid((N + 63) / 64, HD / 64);
        gemm_tiled<<<grid, 256>>>(x, NF, node_W, HD, node_b, p_h0, HD, N, NF, 1);
    }
    {
        dim3 grid((E + 63) / 64, HD / 64);
        gemm_tiled<<<grid, 256>>>(eattr, EF, edge_W, HD, edge_b, p_ea, HD, E, EF, 1);
    }

    // GAT layers
    for (int i = 0; i < NL; i++) {
        const float* Wl   = conv_W + (size_t)i * 2 * HD * HW;  // [128][640]
        const float* Wtop = Wl;
        const float* Wbot = Wl + (size_t)HD * HW;
        const float* attL = conv_att + (size_t)i * NHEAD * 2 * HD;
        const float* bL   = conv_b + i * HD;
        const float* gmL  = conv_g + i * NHEAD;
        const float* btL  = conv_be + i * NHEAD;
        const float* Ain  = (i == 0) ? p_h0 : p_h;

        dim3 gP((N + 63) / 64, HW / 64);
        gemm_tiled<<<gP, 256>>>(Ain, HD, Wtop, HW, nullptr, p_P, HW, N, HD, 0);
        dim3 gQ((E + 63) / 64, HW / 64);
        gemm_tiled<<<gQ, 256>>>(p_ea, HD, Wbot, HW, nullptr, p_Q, HW, E, HD, 0);

        cudaMemsetAsync(p_hagg, 0, (size_t)N * HD * sizeof(float));

        int blocks = (E * 32 + 255) / 256;
        edge_kernel<<<blocks, 256>>>(row, col, attL, gmL, btL, E);

        node_update<<<(N * HD + 255) / 256, 256>>>(bL, N, i == 0, i == NL - 1);
    }

    // readout
    cudaMemsetAsync(p_smax, 0, G * sizeof(unsigned));
    cudaMemsetAsync(p_denom, 0, G * sizeof(float));
    cudaMemsetAsync(p_pooled, 0, (size_t)G * HD * sizeof(float));

    gb_kernel<<<G, HD>>>(gfeat, ga_W1, ga_b1, G);
    score_kernel<<<(N * 32 + 255) / 256, 256>>>(batch, ga_W1, ga_W2, ga_b2, N);
    exp_kernel<<<(N + 255) / 256, 256>>>(batch, N);
    pool_kernel<<<(N * 32 + 255) / 256, 256>>>(batch, N);
    out_kernel<<<G, HD>>>(out_W1, out_b1, out_W2, out_b2, (float*)d_out);
}